// round 3
// baseline (speedup 1.0000x reference)
#include <cuda_runtime.h>
#include <cuda_bf16.h>

#define NBINS 10

// Global scratch (no device allocation allowed). Zero-initialized at module
// load; last block resets after finalize; atomicInc wrap resets g_done.
__device__ float g_sums[NBINS];
__device__ float g_cnts[NBINS];
__device__ unsigned int g_done;

// Predicated packed accumulate: if (bin==b) acc += (v, cf) as f32x2 (fma pipe).
#define ACC_BIN(b)                                                         \
    asm volatile("{\n\t"                                                   \
                 ".reg .pred p;\n\t"                                       \
                 "setp.eq.s32 p, %1, " #b ";\n\t"                          \
                 "@p add.rn.f32x2 %0, %0, %2;\n\t"                         \
                 "}"                                                       \
                 : "+l"(acc[b]) : "r"(bin), "l"(vc));

__global__ __launch_bounds__(256, 6) void ghmc_fused(
    const float4* __restrict__ pred4,
    const int4*   __restrict__ targ4,
    const float4* __restrict__ lw4,
    int n4,
    float* __restrict__ out)
{
    // acc[b] = packed (sum_b : f32 low, count_b : f32 high)
    unsigned long long acc[NBINS];
#pragma unroll
    for (int b = 0; b < NBINS; b++) acc[b] = 0ULL;

    const int stride = gridDim.x * blockDim.x;
    for (int i = blockIdx.x * blockDim.x + threadIdx.x; i < n4; i += stride) {
        float4 p = __ldcs(pred4 + i);
        int4   t = __ldcs(targ4 + i);
        float4 w = __ldcs(lw4 + i);

        float px[4] = {p.x, p.y, p.z, p.w};
        int   tx[4] = {t.x, t.y, t.z, t.w};
        float wx[4] = {w.x, w.y, w.z, w.w};

#pragma unroll
        for (int k = 0; k < 4; k++) {
            float x  = px[k];
            int   ti = tx[k];
            bool  valid = wx[k] > 0.0f;

            // e = exp(-|x|)  (fabs folds into the FMUL operand modifier)
            float e = exp2f(-1.44269504f * fabsf(x));
            float r = __fdividef(1.0f, 1.0f + e);   // sigmoid(|x|)

            // g = |sigmoid(x) - t| = sigmoid(x*(1-2t))
            float xp = (ti != 0) ? -x : x;
            float g  = (xp >= 0.0f) ? r : e * r;

            int bin = min((int)(g * 10.0f), NBINS - 1);

            // bce = max(x,0) - x*t + log1p(e);  log(1+e) = -ln2*log2(r)
            float tf  = (float)ti;
            float l2r = __log2f(r);
            float bce = fmaf(-x, tf, fmaxf(x, 0.0f));
            bce = fmaf(-0.69314718f, l2r, bce);

            float v  = valid ? bce  : 0.0f;
            float cf = valid ? 1.0f : 0.0f;
            unsigned long long vc;
            asm("mov.b64 %0, {%1, %2};" : "=l"(vc) : "f"(v), "f"(cf));

            ACC_BIN(0) ACC_BIN(1) ACC_BIN(2) ACC_BIN(3) ACC_BIN(4)
            ACC_BIN(5) ACC_BIN(6) ACC_BIN(7) ACC_BIN(8) ACC_BIN(9)
        }
    }

    // Warp reduce, still packed (5 shuffle+add per bin).
    const unsigned full = 0xffffffffu;
#pragma unroll
    for (int b = 0; b < NBINS; b++) {
#pragma unroll
        for (int o = 16; o > 0; o >>= 1) {
            unsigned long long other = __shfl_down_sync(full, acc[b], o);
            asm("add.rn.f32x2 %0, %0, %1;" : "+l"(acc[b]) : "l"(other));
        }
    }

    __shared__ float sh_s[NBINS];
    __shared__ float sh_c[NBINS];
    if (threadIdx.x < NBINS) {
        sh_s[threadIdx.x] = 0.0f;
        sh_c[threadIdx.x] = 0.0f;
    }
    __syncthreads();

    if ((threadIdx.x & 31) == 0) {
#pragma unroll
        for (int b = 0; b < NBINS; b++) {
            float sb, cb;
            asm("mov.b64 {%0, %1}, %2;" : "=f"(sb), "=f"(cb) : "l"(acc[b]));
            atomicAdd(&sh_s[b], sb);
            atomicAdd(&sh_c[b], cb);
        }
    }
    __syncthreads();

    if (threadIdx.x < NBINS) {
        atomicAdd(&g_sums[threadIdx.x], sh_s[threadIdx.x]);
        atomicAdd(&g_cnts[threadIdx.x], sh_c[threadIdx.x]);
    }

    // --- last-block finalize ---
    __shared__ bool is_last;
    if (threadIdx.x == 0) {
        __threadfence();
        unsigned r = atomicInc(&g_done, gridDim.x - 1);  // wraps to 0 on last
        is_last = (r == gridDim.x - 1);
    }
    __syncthreads();

    if (is_last && threadIdx.x < 32) {
        __threadfence();
        float contrib = 0.0f;
        float nb = 0.0f;
        if (threadIdx.x < NBINS) {
            float cb = __ldcg(&g_cnts[threadIdx.x]);
            float sb = __ldcg(&g_sums[threadIdx.x]);
            contrib = sb / fmaxf(cb, 1.0f);   // empty bin: sb==0 -> 0
            nb = (cb > 0.0f) ? 1.0f : 0.0f;
            g_cnts[threadIdx.x] = 0.0f;       // reset for next graph replay
            g_sums[threadIdx.x] = 0.0f;
        }
#pragma unroll
        for (int o = 16; o > 0; o >>= 1) {
            contrib += __shfl_down_sync(0xffffffffu, contrib, o);
            nb      += __shfl_down_sync(0xffffffffu, nb, o);
        }
        if (threadIdx.x == 0)
            out[0] = contrib / fmaxf(nb, 1.0f);   // LOSS_WEIGHT = 1.0
    }
}

extern "C" void kernel_launch(void* const* d_in, const int* in_sizes, int n_in,
                              void* d_out, int out_size) {
    const float4* pred4 = (const float4*)d_in[0];
    const int4*   targ4 = (const int4*)d_in[1];
    const float4* lw4   = (const float4*)d_in[2];
    float* out = (float*)d_out;

    int n  = in_sizes[0];
    int n4 = n >> 2;   // 67,108,864 / 4 = 16,777,216

    // 148 SMs x 6 resident blocks -> exactly one full wave.
    ghmc_fused<<<888, 256>>>(pred4, targ4, lw4, n4, out);
}

// round 4
// speedup vs baseline: 1.2346x; 1.2346x over previous
#include <cuda_runtime.h>
#include <cuda_bf16.h>

#define NBINS 10

// Global scratch (no device allocation allowed). Zero-initialized at module
// load; last block resets after finalize; atomicInc wrap resets g_done.
__device__ float g_sums[NBINS];
__device__ float g_cnts[NBINS];
__device__ unsigned int g_done;

__global__ __launch_bounds__(256) void ghmc_fused(
    const float4* __restrict__ pred4,
    const int4*   __restrict__ targ4,
    const float4* __restrict__ lw4,
    int n4,
    float* __restrict__ out)
{
    float s[NBINS];
    float c[NBINS];
#pragma unroll
    for (int b = 0; b < NBINS; b++) { s[b] = 0.0f; c[b] = 0.0f; }

    const int stride = gridDim.x * blockDim.x;
    for (int i = blockIdx.x * blockDim.x + threadIdx.x; i < n4; i += stride) {
        float4 p = pred4[i];
        int4   t = targ4[i];
        float4 w = lw4[i];

        float px[4] = {p.x, p.y, p.z, p.w};
        int   tx[4] = {t.x, t.y, t.z, t.w};
        float wx[4] = {w.x, w.y, w.z, w.w};

#pragma unroll
        for (int k = 0; k < 4; k++) {
            float x  = px[k];
            int   ti = tx[k];
            bool  valid = wx[k] > 0.0f;

            // e = exp(-|x|) via exp2 (fabs/neg fold into operand modifiers)
            float e = exp2f(-1.44269504f * fabsf(x));
            float r = __fdividef(1.0f, 1.0f + e);   // sigmoid(|x|)

            // g = |sigmoid(x) - t| = sigmoid(x*(1-2t))
            float xp = (ti != 0) ? -x : x;
            float g  = (xp >= 0.0f) ? r : e * r;

            int bin = min((int)(g * 10.0f), NBINS - 1);

            // bce = max(x,0) - x*t + log1p(e);  log(1+e) = -ln2*log2(r)
            float bce = fmaf(-x, (float)ti, fmaxf(x, 0.0f));
            bce = fmaf(-0.69314718f, __log2f(r), bce);

            float v  = valid ? bce  : 0.0f;
            float cf = valid ? 1.0f : 0.0f;

#pragma unroll
            for (int b = 0; b < NBINS; b++) {
                bool hit = (bin == b);
                s[b] = hit ? s[b] + v  : s[b];
                c[b] = hit ? c[b] + cf : c[b];
            }
        }
    }

    // Warp butterfly reduce all 20 accumulators.
    const unsigned full = 0xffffffffu;
#pragma unroll
    for (int b = 0; b < NBINS; b++) {
#pragma unroll
        for (int o = 16; o > 0; o >>= 1) {
            s[b] += __shfl_down_sync(full, s[b], o);
            c[b] += __shfl_down_sync(full, c[b], o);
        }
    }

    __shared__ float sh_s[NBINS];
    __shared__ float sh_c[NBINS];
    if (threadIdx.x < NBINS) {
        sh_s[threadIdx.x] = 0.0f;
        sh_c[threadIdx.x] = 0.0f;
    }
    __syncthreads();

    if ((threadIdx.x & 31) == 0) {
#pragma unroll
        for (int b = 0; b < NBINS; b++) {
            atomicAdd(&sh_s[b], s[b]);
            atomicAdd(&sh_c[b], c[b]);
        }
    }
    __syncthreads();

    if (threadIdx.x < NBINS) {
        atomicAdd(&g_sums[threadIdx.x], sh_s[threadIdx.x]);
        atomicAdd(&g_cnts[threadIdx.x], sh_c[threadIdx.x]);
    }

    // --- last-block finalize (threadfence reduction pattern) ---
    __shared__ bool is_last;
    if (threadIdx.x == 0) {
        __threadfence();
        unsigned r = atomicInc(&g_done, gridDim.x - 1);  // wraps to 0 on last
        is_last = (r == gridDim.x - 1);
    }
    __syncthreads();

    if (is_last && threadIdx.x < 32) {
        __threadfence();
        float contrib = 0.0f;
        float nb = 0.0f;
        if (threadIdx.x < NBINS) {
            float cb = __ldcg(&g_cnts[threadIdx.x]);
            float sb = __ldcg(&g_sums[threadIdx.x]);
            contrib = sb / fmaxf(cb, 1.0f);   // empty bin: sb==0 -> 0
            nb = (cb > 0.0f) ? 1.0f : 0.0f;
            g_cnts[threadIdx.x] = 0.0f;       // reset for next graph replay
            g_sums[threadIdx.x] = 0.0f;
        }
#pragma unroll
        for (int o = 16; o > 0; o >>= 1) {
            contrib += __shfl_down_sync(0xffffffffu, contrib, o);
            nb      += __shfl_down_sync(0xffffffffu, nb, o);
        }
        if (threadIdx.x == 0)
            out[0] = contrib / fmaxf(nb, 1.0f);   // LOSS_WEIGHT = 1.0
    }
}

extern "C" void kernel_launch(void* const* d_in, const int* in_sizes, int n_in,
                              void* d_out, int out_size) {
    const float4* pred4 = (const float4*)d_in[0];
    const int4*   targ4 = (const int4*)d_in[1];
    const float4* lw4   = (const float4*)d_in[2];
    float* out = (float*)d_out;

    int n  = in_sizes[0];
    int n4 = n >> 2;   // 67,108,864 / 4 = 16,777,216

    ghmc_fused<<<1184, 256>>>(pred4, targ4, lw4, n4, out);
}